// round 6
// baseline (speedup 1.0000x reference)
#include <cuda_runtime.h>
#include <cuda_fp16.h>
#include <math_constants.h>

// CollectNeighbourAverageAndMax: V=100000, K=32, F=64
// out[v, 0:64]   = sum_k x[idxs[v,k], :] / K
// out[v, 64:128] = max_k x[idxs[v,k], :]
//
// Two-kernel scheme:
//  1) convert: x (fp32, 25.6MB) -> xh (fp16, 12.8MB) in __device__ scratch.
//     Pure HBM stream, ~5us.
//  2) gather: warp per vertex, lane l owns features [2l,2l+1] as ONE half2.
//     Per neighbor the warp reads a 128B row = 1 L1 wavefront (vs 2 for fp32),
//     halving the L2 gather traffic (819MB -> 410MB) that R1-R5 proved to be
//     the roofline. Accumulation in fp32; fp16 round-off ~4.9e-4 rel worst
//     case, well under the 1e-3 gate.

static constexpr int V = 100000;
static constexpr int K = 32;
static constexpr int F = 64;

// fp16 copy of x: V*F halves = 12.8MB static scratch (allowed; no allocs).
__device__ __half2 g_xh[(size_t)V * F / 2];

struct alignas(8) half4 { __half2 a, b; };

__global__ __launch_bounds__(256) void convert_kernel(const float* __restrict__ x)
{
    const int i = blockIdx.x * blockDim.x + threadIdx.x;   // over V*F/4 float4s
    if (i >= V * F / 4) return;
    const float4 v = reinterpret_cast<const float4*>(x)[i];
    half4 h;
    h.a = __floats2half2_rn(v.x, v.y);
    h.b = __floats2half2_rn(v.z, v.w);
    reinterpret_cast<half4*>(g_xh)[i] = h;
}

__global__ __launch_bounds__(256) void gather_kernel(
    const int* __restrict__ idxs,
    float* __restrict__ out)
{
    const int warp_id = (blockIdx.x * blockDim.x + threadIdx.x) >> 5;
    const int lane = threadIdx.x & 31;
    if (warp_id >= V) return;

    // Coalesced index load; pre-scale to row offset in half2 units (idx * 32).
    const int my_row = idxs[warp_id * K + lane] * (F / 2);

    float2 s = make_float2(0.0f, 0.0f);
    float2 m = make_float2(-CUDART_INF_F, -CUDART_INF_F);

    const __half2* xb = g_xh + lane;   // lane's half2 column within a row

    #pragma unroll
    for (int k = 0; k < K; ++k) {
        const int row = __shfl_sync(0xffffffffu, my_row, k);
        const float2 v = __half22float2(xb[row]);   // LDG.32: 128B/warp = 1 wf
        s.x += v.x;
        s.y += v.y;
        m.x = fmaxf(m.x, v.x);
        m.y = fmaxf(m.y, v.y);
    }

    constexpr float inv_k = 1.0f / K;
    s.x *= inv_k;
    s.y *= inv_k;

    float* o = out + (size_t)warp_id * (2 * F);
    *reinterpret_cast<float2*>(o + 2 * lane) = s;       // mean part
    *reinterpret_cast<float2*>(o + F + 2 * lane) = m;   // max part
}

extern "C" void kernel_launch(void* const* d_in, const int* in_sizes, int n_in,
                              void* d_out, int out_size)
{
    const float* x = (const float*)d_in[0];
    const int* idxs = (const int*)d_in[1];
    float* out = (float*)d_out;

    // Kernel 1: fp32 -> fp16 conversion (V*F/4 = 1.6M float4s).
    const int conv_elems = V * F / 4;
    convert_kernel<<<(conv_elems + 255) / 256, 256>>>(x);

    // Kernel 2: gather + reduce. 8 warps/block -> 8 vertices/block.
    const int warps_per_block = 256 / 32;
    const int blocks = (V + warps_per_block - 1) / warps_per_block;  // 12500
    gather_kernel<<<blocks, 256>>>(idxs, out);
}